// round 2
// baseline (speedup 1.0000x reference)
#include <cuda_runtime.h>
#include <math.h>

// Problem constants (fixed by the dataset)
#define EPS    1e-6f
#define N_EP   2048
#define NS     5
#define NQ     8
#define SLOTS  13          // NS + NQ
#define D      256
#define NROW   16384       // N_EP * NQ

// GEMM tiling
#define TM     64
#define TN     128
#define TK     16
#define NTH    128
#define QSS    68          // TM + 4 pad
#define ASS    132         // TN + 4 pad
#define NTTILE (N_EP / TN) // 16
#define NCHUNK (D / TK)    // 16

__device__ __align__(256) float g_anchors[N_EP * D];
__device__ __align__(256) float g_ccol[N_EP];      // -a_sq + 2*eps*a_sum per anchor
__device__ double g_loss;
__device__ int    g_correct;
__device__ int    g_lab32;   // 1 if label buffer is int32, 0 if int64

// Zero accumulators + detect label dtype. jnp.int64 silently becomes int32
// when JAX x64 is disabled; detect from the data: int64 labels < 2048 have
// zero high words, int32 data read as u64 has high words = next label (rarely 0).
__global__ void init_kernel(const unsigned long long* __restrict__ lab) {
    unsigned long long v = lab[threadIdx.x];          // 32 threads, in-bounds either way
    unsigned b = __ballot_sync(0xFFFFFFFFu, (v >> 32) != 0ull);
    if (threadIdx.x == 0) {
        g_loss = 0.0;
        g_correct = 0;
        g_lab32 = (b != 0u) ? 1 : 0;
    }
}

// One block per episode: anchor = mean of 5 supports, plus column constant.
__global__ void prep_kernel(const float* __restrict__ x) {
    int i = blockIdx.x;
    int d = threadIdx.x;           // 256 threads == D
    const float* xr = x + (size_t)i * SLOTS * D + d;
    float a = (xr[0] + xr[D] + xr[2 * D] + xr[3 * D] + xr[4 * D]) * 0.2f;
    g_anchors[i * D + d] = a;

    float sq = a * a, sm = a;
#pragma unroll
    for (int o = 16; o; o >>= 1) {
        sq += __shfl_xor_sync(0xFFFFFFFFu, sq, o);
        sm += __shfl_xor_sync(0xFFFFFFFFu, sm, o);
    }
    __shared__ float ssq[8], ssm[8];
    if ((threadIdx.x & 31) == 0) {
        ssq[threadIdx.x >> 5] = sq;
        ssm[threadIdx.x >> 5] = sm;
    }
    __syncthreads();
    if (threadIdx.x == 0) {
        float t1 = 0.f, t2 = 0.f;
#pragma unroll
        for (int k = 0; k < 8; k++) { t1 += ssq[k]; t2 += ssm[k]; }
        g_ccol[i] = -t1 + 2.0f * EPS * t2;
    }
}

// Shared memory: GEMM staging buffers, reused (union) for the final reduction.
union SmemU {
    struct {
        float Qs[2][TK][QSS];
        float As[2][TK][ASS];
    } g;
    struct {
        float RM[TM][16];
        float RS[TM][16];
        float RL[TM][16];
        float RBV[TM][16];
        int   RBI[TM][16];
        float LOGP[TM];
        int   CORR[TM];
    } r;
};

// Fused GEMM + softmax. Each block: 64 query rows x all 2048 anchors.
// logits' = 2*(q . a) + ccol[c]  (row constants cancel in softmax/argmax/logp).
// Each lane keeps a PRIVATE online softmax over its own 128 columns; one
// shared-memory merge at the end (no cross-lane shuffles in the hot path).
__global__ __launch_bounds__(NTH) void gemm_softmax_kernel(
    const float* __restrict__ x, const void* __restrict__ label_raw) {
    __shared__ SmemU u;

    const int tid = threadIdx.x;
    const int tn = tid & 15;   // 16 threads over N
    const int tm = tid >> 4;   // 8 threads over M
    const int r0 = blockIdx.x * TM;

    const int lab32 = g_lab32;
    const int* lab_i32 = (const int*)label_raw;
    const long long* lab_i64 = (const long long*)label_raw;

    // --- global-load descriptors (rows fixed per thread) ---
    const float* qsrc[2];
    int qdk[2], qdr[2];
#pragma unroll
    for (int j = 0; j < 2; j++) {
        int flat = tid + j * NTH;          // 0..255 -> 64 rows x 4 segs
        int row = flat >> 2, seg = flat & 3;
        int r = r0 + row;
        qsrc[j] = x + ((size_t)(r >> 3) * SLOTS + NS + (r & 7)) * D + seg * 4;
        qdk[j] = seg * 4;
        qdr[j] = row;
    }
    int arow[4], adk[4];
#pragma unroll
    for (int j = 0; j < 4; j++) {
        int flat = tid + j * NTH;          // 0..511 -> 128 rows x 4 segs
        arow[j] = flat >> 2;
        adk[j] = (flat & 3) * 4;
    }

    int llab[8];
#pragma unroll
    for (int i = 0; i < 8; i++) {
        int ep = (r0 + tm * 8 + i) >> 3;
        llab[i] = lab32 ? lab_i32[ep] : (int)lab_i64[ep];
    }

    // per-(row,lane) private online-softmax state over this lane's columns
    float m_[8], s_[8], llog_[8], bv_[8];
    int bi_[8];
#pragma unroll
    for (int i = 0; i < 8; i++) {
        m_[i] = -INFINITY; s_[i] = 0.f; llog_[i] = -INFINITY;
        bv_[i] = -INFINITY; bi_[i] = 0x7fffffff;
    }

    for (int nt = 0; nt < NTTILE; nt++) {
        const int n0 = nt * TN;
        const float* abase = g_anchors + (size_t)n0 * D;

        float acc[8][8];
#pragma unroll
        for (int i = 0; i < 8; i++)
#pragma unroll
            for (int j = 0; j < 8; j++) acc[i][j] = 0.f;

        float4 qv[2], av[4];
        // prologue: chunk 0 -> buf 0
#pragma unroll
        for (int j = 0; j < 2; j++) qv[j] = *(const float4*)(qsrc[j]);
#pragma unroll
        for (int j = 0; j < 4; j++) av[j] = *(const float4*)(abase + arow[j] * D + adk[j]);
#pragma unroll
        for (int j = 0; j < 2; j++) {
            u.g.Qs[0][qdk[j] + 0][qdr[j]] = qv[j].x;
            u.g.Qs[0][qdk[j] + 1][qdr[j]] = qv[j].y;
            u.g.Qs[0][qdk[j] + 2][qdr[j]] = qv[j].z;
            u.g.Qs[0][qdk[j] + 3][qdr[j]] = qv[j].w;
        }
#pragma unroll
        for (int j = 0; j < 4; j++) {
            u.g.As[0][adk[j] + 0][arow[j]] = av[j].x;
            u.g.As[0][adk[j] + 1][arow[j]] = av[j].y;
            u.g.As[0][adk[j] + 2][arow[j]] = av[j].z;
            u.g.As[0][adk[j] + 3][arow[j]] = av[j].w;
        }
        __syncthreads();

#pragma unroll 1
        for (int c = 0; c < NCHUNK; c++) {
            const int cb = c & 1;
            const int nb = (c + 1) & 1;
            if (c + 1 < NCHUNK) {   // uniform condition
                int kk = (c + 1) * TK;
#pragma unroll
                for (int j = 0; j < 2; j++) qv[j] = *(const float4*)(qsrc[j] + kk);
#pragma unroll
                for (int j = 0; j < 4; j++) av[j] = *(const float4*)(abase + arow[j] * D + adk[j] + kk);
            }
#pragma unroll
            for (int k = 0; k < TK; k++) {
                float4 qa = *(const float4*)&u.g.Qs[cb][k][tm * 8];
                float4 qb = *(const float4*)&u.g.Qs[cb][k][tm * 8 + 4];
                float4 aa = *(const float4*)&u.g.As[cb][k][tn * 8];
                float4 ab = *(const float4*)&u.g.As[cb][k][tn * 8 + 4];
                float qr[8] = {qa.x, qa.y, qa.z, qa.w, qb.x, qb.y, qb.z, qb.w};
                float ar[8] = {aa.x, aa.y, aa.z, aa.w, ab.x, ab.y, ab.z, ab.w};
#pragma unroll
                for (int i = 0; i < 8; i++)
#pragma unroll
                    for (int j = 0; j < 8; j++)
                        acc[i][j] = fmaf(qr[i], ar[j], acc[i][j]);
            }
            if (c + 1 < NCHUNK) {
#pragma unroll
                for (int j = 0; j < 2; j++) {
                    u.g.Qs[nb][qdk[j] + 0][qdr[j]] = qv[j].x;
                    u.g.Qs[nb][qdk[j] + 1][qdr[j]] = qv[j].y;
                    u.g.Qs[nb][qdk[j] + 2][qdr[j]] = qv[j].z;
                    u.g.Qs[nb][qdk[j] + 3][qdr[j]] = qv[j].w;
                }
#pragma unroll
                for (int j = 0; j < 4; j++) {
                    u.g.As[nb][adk[j] + 0][arow[j]] = av[j].x;
                    u.g.As[nb][adk[j] + 1][arow[j]] = av[j].y;
                    u.g.As[nb][adk[j] + 2][arow[j]] = av[j].z;
                    u.g.As[nb][adk[j] + 3][arow[j]] = av[j].w;
                }
                __syncthreads();
            }
        }

        // ---- per-lane epilogue (no cross-lane communication) ----
        float cc[8];
        {
            float4 c0 = *(const float4*)&g_ccol[n0 + tn * 8];
            float4 c1 = *(const float4*)&g_ccol[n0 + tn * 8 + 4];
            cc[0] = c0.x; cc[1] = c0.y; cc[2] = c0.z; cc[3] = c0.w;
            cc[4] = c1.x; cc[5] = c1.y; cc[6] = c1.z; cc[7] = c1.w;
        }
#pragma unroll
        for (int i = 0; i < 8; i++) {
            float lg[8];
            float tmax = -INFINITY;
#pragma unroll
            for (int j = 0; j < 8; j++) {
                lg[j] = 2.0f * acc[i][j] + cc[j];
                tmax = fmaxf(tmax, lg[j]);
            }
            float newm = fmaxf(m_[i], tmax);
            float p = 0.f;
#pragma unroll
            for (int j = 0; j < 8; j++) p += __expf(lg[j] - newm);
            s_[i] = s_[i] * __expf(m_[i] - newm) + p;
            m_[i] = newm;
#pragma unroll
            for (int j = 0; j < 8; j++) {
                int col = n0 + tn * 8 + j;
                if (col == llab[i]) llog_[i] = lg[j];
                if (lg[j] > bv_[i]) { bv_[i] = lg[j]; bi_[i] = col; } // cols visited in increasing order
            }
        }
        // Safe without a barrier here: last smem reads of this tile (c=NCHUNK-1,
        // buf1) are ordered before the next prologue's buf0 writes by the
        // barrier at the end of c=NCHUNK-2.
    }

    // ---- final merge via shared memory (aliased over GEMM buffers) ----
    __syncthreads();   // all GEMM smem reads complete before aliasing
#pragma unroll
    for (int i = 0; i < 8; i++) {
        int row = tm * 8 + i;
        u.r.RM[row][tn]  = m_[i];
        u.r.RS[row][tn]  = s_[i];
        u.r.RL[row][tn]  = llog_[i];
        u.r.RBV[row][tn] = bv_[i];
        u.r.RBI[row][tn] = bi_[i];
    }
    __syncthreads();

    if (tid < TM) {
        int row = tid;
        float M = -INFINITY;
#pragma unroll
        for (int t = 0; t < 16; t++) M = fmaxf(M, u.r.RM[row][t]);
        float S = 0.f;
#pragma unroll
        for (int t = 0; t < 16; t++) S += u.r.RS[row][t] * __expf(u.r.RM[row][t] - M);
        float L = -INFINITY;
#pragma unroll
        for (int t = 0; t < 16; t++) L = fmaxf(L, u.r.RL[row][t]);
        float BV = -INFINITY; int BI = 0x7fffffff;
#pragma unroll
        for (int t = 0; t < 16; t++) {
            float v = u.r.RBV[row][t]; int ix = u.r.RBI[row][t];
            if (v > BV || (v == BV && ix < BI)) { BV = v; BI = ix; }
        }
        int ep = (r0 + row) >> 3;
        int lv = lab32 ? lab_i32[ep] : (int)lab_i64[ep];
        u.r.LOGP[row] = L - M - logf(S);
        u.r.CORR[row] = (BI == lv) ? 1 : 0;
    }
    __syncthreads();

    if (tid == 0) {
        double ls = 0.0; int cs = 0;
#pragma unroll
        for (int r = 0; r < TM; r++) { ls += (double)u.r.LOGP[r]; cs += u.r.CORR[r]; }
        atomicAdd(&g_loss, ls);
        atomicAdd(&g_correct, cs);
    }
}

__global__ void final_kernel(float* out, int out_size) {
    if (out_size > 0) out[0] = (float)(-g_loss / (double)NROW);
    if (out_size > 1) out[1] = (float)g_correct * (100.0f / (float)NROW);
}

extern "C" void kernel_launch(void* const* d_in, const int* in_sizes, int n_in,
                              void* d_out, int out_size) {
    const float* x = (const float*)d_in[0];
    const unsigned long long* label = (const unsigned long long*)d_in[1];
    float* out = (float*)d_out;

    init_kernel<<<1, 32>>>(label);
    prep_kernel<<<N_EP, D>>>(x);
    gemm_softmax_kernel<<<NROW / TM, NTH>>>(x, (const void*)label);
    final_kernel<<<1, 1>>>(out, out_size);
}

// round 3
// speedup vs baseline: 1.1917x; 1.1917x over previous
#include <cuda_runtime.h>
#include <math.h>

// Problem constants (fixed by the dataset)
#define EPS    1e-6f
#define N_EP   2048
#define NS     5
#define NQ     8
#define SLOTS  13          // NS + NQ
#define D      256
#define NROW   16384       // N_EP * NQ

// GEMM tiling
#define TM     64
#define TN     128
#define TK     16
#define NTH    128
#define QSS    68          // TM + 4 pad
#define ASS    132         // TN + 4 pad
#define NTTILE (N_EP / TN) // 16
#define NCHUNK (D / TK)    // 16

__device__ __align__(256) float g_anchors[N_EP * D];
__device__ __align__(256) float g_ccol[N_EP];      // -a_sq + 2*eps*a_sum per anchor
__device__ double g_loss;
__device__ int    g_correct;
__device__ int    g_lab32;   // 1 if label buffer is int32, 0 if int64

// ---- packed f32x2 helpers (Blackwell FFMA2 path; ptxas won't auto-fuse) ----
__device__ __forceinline__ unsigned long long pack2(float lo, float hi) {
    unsigned long long r;
    asm("mov.b64 %0, {%1, %2};" : "=l"(r) : "f"(lo), "f"(hi));
    return r;
}
__device__ __forceinline__ void unpack2(float& lo, float& hi, unsigned long long v) {
    asm("mov.b64 {%0, %1}, %2;" : "=f"(lo), "=f"(hi) : "l"(v));
}
__device__ __forceinline__ void ffma2(unsigned long long& acc,
                                      unsigned long long a, unsigned long long b) {
    asm("fma.rn.f32x2 %0, %1, %2, %0;" : "+l"(acc) : "l"(a), "l"(b));
}

// Zero accumulators + detect label dtype (jnp.int64 silently becomes int32
// when JAX x64 is disabled; int64 labels < 2048 have zero high words).
__global__ void init_kernel(const unsigned long long* __restrict__ lab) {
    unsigned long long v = lab[threadIdx.x];          // 32 threads, in-bounds either way
    unsigned b = __ballot_sync(0xFFFFFFFFu, (v >> 32) != 0ull);
    if (threadIdx.x == 0) {
        g_loss = 0.0;
        g_correct = 0;
        g_lab32 = (b != 0u) ? 1 : 0;
    }
}

// One block per episode: anchor = mean of 5 supports, plus column constant.
__global__ void prep_kernel(const float* __restrict__ x) {
    int i = blockIdx.x;
    int d = threadIdx.x;           // 256 threads == D
    const float* xr = x + (size_t)i * SLOTS * D + d;
    float a = (xr[0] + xr[D] + xr[2 * D] + xr[3 * D] + xr[4 * D]) * 0.2f;
    g_anchors[i * D + d] = a;

    float sq = a * a, sm = a;
#pragma unroll
    for (int o = 16; o; o >>= 1) {
        sq += __shfl_xor_sync(0xFFFFFFFFu, sq, o);
        sm += __shfl_xor_sync(0xFFFFFFFFu, sm, o);
    }
    __shared__ float ssq[8], ssm[8];
    if ((threadIdx.x & 31) == 0) {
        ssq[threadIdx.x >> 5] = sq;
        ssm[threadIdx.x >> 5] = sm;
    }
    __syncthreads();
    if (threadIdx.x == 0) {
        float t1 = 0.f, t2 = 0.f;
#pragma unroll
        for (int k = 0; k < 8; k++) { t1 += ssq[k]; t2 += ssm[k]; }
        g_ccol[i] = -t1 + 2.0f * EPS * t2;
    }
}

// Shared memory: GEMM staging buffers, reused (union) for the final reduction.
union SmemU {
    struct {
        float Qs[2][TK][QSS];
        float As[2][TK][ASS];
    } g;
    struct {
        float RM[TM][16];
        float RS[TM][16];
        float RL[TM][16];
        float RBV[TM][16];
        int   RBI[TM][16];
        float LOGP[TM];
        int   CORR[TM];
    } r;
};

// Fused GEMM + softmax. Each block: 64 query rows x all 2048 anchors.
// logits' = 2*(q . a) + ccol[c]  (row constants cancel in softmax/argmax/logp).
__global__ __launch_bounds__(NTH, 2) void gemm_softmax_kernel(
    const float* __restrict__ x, const void* __restrict__ label_raw) {
    __shared__ SmemU u;

    const int tid = threadIdx.x;
    const int tn = tid & 15;   // 16 threads over N
    const int tm = tid >> 4;   // 8 threads over M
    const int r0 = blockIdx.x * TM;

    const int lab32 = g_lab32;
    const int* lab_i32 = (const int*)label_raw;
    const long long* lab_i64 = (const long long*)label_raw;

    // --- global-load descriptors (rows fixed per thread) ---
    const float* qsrc[2];
    int qdk[2], qdr[2];
#pragma unroll
    for (int j = 0; j < 2; j++) {
        int flat = tid + j * NTH;          // 0..255 -> 64 rows x 4 segs
        int row = flat >> 2, seg = flat & 3;
        int r = r0 + row;
        qsrc[j] = x + ((size_t)(r >> 3) * SLOTS + NS + (r & 7)) * D + seg * 4;
        qdk[j] = seg * 4;
        qdr[j] = row;
    }
    int arow[4], adk[4];
#pragma unroll
    for (int j = 0; j < 4; j++) {
        int flat = tid + j * NTH;          // 0..511 -> 128 rows x 4 segs
        arow[j] = flat >> 2;
        adk[j] = (flat & 3) * 4;
    }

    int llab[8];
#pragma unroll
    for (int i = 0; i < 8; i++) {
        int ep = (r0 + tm * 8 + i) >> 3;
        llab[i] = lab32 ? lab_i32[ep] : (int)lab_i64[ep];
    }

    // per-(row,lane) private online-softmax state over this lane's columns
    float m_[8], s_[8], llog_[8], bv_[8];
    int bi_[8];
#pragma unroll
    for (int i = 0; i < 8; i++) {
        m_[i] = -INFINITY; s_[i] = 0.f; llog_[i] = -INFINITY;
        bv_[i] = -INFINITY; bi_[i] = 0x7fffffff;
    }

    for (int nt = 0; nt < NTTILE; nt++) {
        const int n0 = nt * TN;
        const float* abase = g_anchors + (size_t)n0 * D;

        // 8 rows x 4 column-pairs of packed fp32x2 accumulators
        unsigned long long acc2[8][4];
        const unsigned long long z2 = pack2(0.f, 0.f);
#pragma unroll
        for (int i = 0; i < 8; i++)
#pragma unroll
            for (int jp = 0; jp < 4; jp++) acc2[i][jp] = z2;

        float4 qv[2], av[4];
        // prologue: chunk 0 -> buf 0
#pragma unroll
        for (int j = 0; j < 2; j++) qv[j] = *(const float4*)(qsrc[j]);
#pragma unroll
        for (int j = 0; j < 4; j++) av[j] = *(const float4*)(abase + arow[j] * D + adk[j]);
#pragma unroll
        for (int j = 0; j < 2; j++) {
            u.g.Qs[0][qdk[j] + 0][qdr[j]] = qv[j].x;
            u.g.Qs[0][qdk[j] + 1][qdr[j]] = qv[j].y;
            u.g.Qs[0][qdk[j] + 2][qdr[j]] = qv[j].z;
            u.g.Qs[0][qdk[j] + 3][qdr[j]] = qv[j].w;
        }
#pragma unroll
        for (int j = 0; j < 4; j++) {
            u.g.As[0][adk[j] + 0][arow[j]] = av[j].x;
            u.g.As[0][adk[j] + 1][arow[j]] = av[j].y;
            u.g.As[0][adk[j] + 2][arow[j]] = av[j].z;
            u.g.As[0][adk[j] + 3][arow[j]] = av[j].w;
        }
        __syncthreads();

#pragma unroll 1
        for (int c = 0; c < NCHUNK; c++) {
            const int cb = c & 1;
            const int nb = (c + 1) & 1;
            if (c + 1 < NCHUNK) {   // uniform condition
                int kk = (c + 1) * TK;
#pragma unroll
                for (int j = 0; j < 2; j++) qv[j] = *(const float4*)(qsrc[j] + kk);
#pragma unroll
                for (int j = 0; j < 4; j++) av[j] = *(const float4*)(abase + arow[j] * D + adk[j] + kk);
            }
#pragma unroll
            for (int k = 0; k < TK; k++) {
                float4 qa = *(const float4*)&u.g.Qs[cb][k][tm * 8];
                float4 qb = *(const float4*)&u.g.Qs[cb][k][tm * 8 + 4];
                float4 aa = *(const float4*)&u.g.As[cb][k][tn * 8];
                float4 ab = *(const float4*)&u.g.As[cb][k][tn * 8 + 4];
                // A pairs: adjacent components of an LDS.128 quad (aligned reg pair)
                unsigned long long a2[4];
                a2[0] = pack2(aa.x, aa.y); a2[1] = pack2(aa.z, aa.w);
                a2[2] = pack2(ab.x, ab.y); a2[3] = pack2(ab.z, ab.w);
                float qs[8] = {qa.x, qa.y, qa.z, qa.w, qb.x, qb.y, qb.z, qb.w};
#pragma unroll
                for (int i = 0; i < 8; i++) {
                    unsigned long long q2 = pack2(qs[i], qs[i]);
#pragma unroll
                    for (int jp = 0; jp < 4; jp++)
                        ffma2(acc2[i][jp], q2, a2[jp]);
                }
            }
            if (c + 1 < NCHUNK) {
#pragma unroll
                for (int j = 0; j < 2; j++) {
                    u.g.Qs[nb][qdk[j] + 0][qdr[j]] = qv[j].x;
                    u.g.Qs[nb][qdk[j] + 1][qdr[j]] = qv[j].y;
                    u.g.Qs[nb][qdk[j] + 2][qdr[j]] = qv[j].z;
                    u.g.Qs[nb][qdk[j] + 3][qdr[j]] = qv[j].w;
                }
#pragma unroll
                for (int j = 0; j < 4; j++) {
                    u.g.As[nb][adk[j] + 0][arow[j]] = av[j].x;
                    u.g.As[nb][adk[j] + 1][arow[j]] = av[j].y;
                    u.g.As[nb][adk[j] + 2][arow[j]] = av[j].z;
                    u.g.As[nb][adk[j] + 3][arow[j]] = av[j].w;
                }
                __syncthreads();
            }
        }

        // ---- per-lane epilogue (no cross-lane communication) ----
        float cc[8];
        {
            float4 c0 = *(const float4*)&g_ccol[n0 + tn * 8];
            float4 c1 = *(const float4*)&g_ccol[n0 + tn * 8 + 4];
            cc[0] = c0.x; cc[1] = c0.y; cc[2] = c0.z; cc[3] = c0.w;
            cc[4] = c1.x; cc[5] = c1.y; cc[6] = c1.z; cc[7] = c1.w;
        }
#pragma unroll
        for (int i = 0; i < 8; i++) {
            float lg[8];
            float tmax = -INFINITY;
#pragma unroll
            for (int jp = 0; jp < 4; jp++) {
                float lo, hi;
                unpack2(lo, hi, acc2[i][jp]);
                lg[2 * jp]     = 2.0f * lo + cc[2 * jp];
                lg[2 * jp + 1] = 2.0f * hi + cc[2 * jp + 1];
            }
#pragma unroll
            for (int j = 0; j < 8; j++) tmax = fmaxf(tmax, lg[j]);
            float newm = fmaxf(m_[i], tmax);
            float p = 0.f;
#pragma unroll
            for (int j = 0; j < 8; j++) p += __expf(lg[j] - newm);
            s_[i] = s_[i] * __expf(m_[i] - newm) + p;
            m_[i] = newm;
#pragma unroll
            for (int j = 0; j < 8; j++) {
                int col = n0 + tn * 8 + j;
                if (col == llab[i]) llog_[i] = lg[j];
                if (lg[j] > bv_[i]) { bv_[i] = lg[j]; bi_[i] = col; } // cols visited in increasing order
            }
        }
        // Safe without a barrier here: last smem reads of this tile (c=NCHUNK-1,
        // buf1) are ordered before the next prologue's buf0 writes by the
        // barrier at the end of c=NCHUNK-2.
    }

    // ---- final merge via shared memory (aliased over GEMM buffers) ----
    __syncthreads();   // all GEMM smem reads complete before aliasing
#pragma unroll
    for (int i = 0; i < 8; i++) {
        int row = tm * 8 + i;
        u.r.RM[row][tn]  = m_[i];
        u.r.RS[row][tn]  = s_[i];
        u.r.RL[row][tn]  = llog_[i];
        u.r.RBV[row][tn] = bv_[i];
        u.r.RBI[row][tn] = bi_[i];
    }
    __syncthreads();

    if (tid < TM) {
        int row = tid;
        float M = -INFINITY;
#pragma unroll
        for (int t = 0; t < 16; t++) M = fmaxf(M, u.r.RM[row][t]);
        float S = 0.f;
#pragma unroll
        for (int t = 0; t < 16; t++) S += u.r.RS[row][t] * __expf(u.r.RM[row][t] - M);
        float L = -INFINITY;
#pragma unroll
        for (int t = 0; t < 16; t++) L = fmaxf(L, u.r.RL[row][t]);
        float BV = -INFINITY; int BI = 0x7fffffff;
#pragma unroll
        for (int t = 0; t < 16; t++) {
            float v = u.r.RBV[row][t]; int ix = u.r.RBI[row][t];
            if (v > BV || (v == BV && ix < BI)) { BV = v; BI = ix; }
        }
        int ep = (r0 + row) >> 3;
        int lv = lab32 ? lab_i32[ep] : (int)lab_i64[ep];
        u.r.LOGP[row] = L - M - logf(S);
        u.r.CORR[row] = (BI == lv) ? 1 : 0;
    }
    __syncthreads();

    if (tid == 0) {
        double ls = 0.0; int cs = 0;
#pragma unroll
        for (int r = 0; r < TM; r++) { ls += (double)u.r.LOGP[r]; cs += u.r.CORR[r]; }
        atomicAdd(&g_loss, ls);
        atomicAdd(&g_correct, cs);
    }
}

__global__ void final_kernel(float* out, int out_size) {
    if (out_size > 0) out[0] = (float)(-g_loss / (double)NROW);
    if (out_size > 1) out[1] = (float)g_correct * (100.0f / (float)NROW);
}

extern "C" void kernel_launch(void* const* d_in, const int* in_sizes, int n_in,
                              void* d_out, int out_size) {
    const float* x = (const float*)d_in[0];
    const unsigned long long* label = (const unsigned long long*)d_in[1];
    float* out = (float*)d_out;

    init_kernel<<<1, 32>>>(label);
    prep_kernel<<<N_EP, D>>>(x);
    gemm_softmax_kernel<<<NROW / TM, NTH>>>(x, (const void*)label);
    final_kernel<<<1, 1>>>(out, out_size);
}

// round 5
// speedup vs baseline: 3.6076x; 3.0272x over previous
#include <cuda_runtime.h>
#include <cuda_fp16.h>
#include <math.h>
#include <stdint.h>

// ---------------- problem constants ----------------
#define EPS    1e-6f
#define N_EP   2048
#define NS     5
#define SLOTS  13
#define D      256
#define NROW   16384
#define KEXT   512              // [hi(256) | lo(256)] fp16 split
#define MT     128              // M rows per CTA
#define NT     64               // N cols per tile
#define NTILES (N_EP / NT)      // 32
#define NKC    (KEXT / 16)      // 32 k-steps
#define LOG2E  1.4426950408889634f
#define SC2    2.8853900817779268f   // 2*log2(e)
#define LN2    0.6931471805599453

// ---------------- device globals ----------------
__device__ __align__(256) __half g_aext[N_EP * KEXT];  // anchors split [n][512]
__device__ __align__(256) float  g_cc2[N_EP];          // (-a_sq + 2*eps*a_sum)*log2e
__device__ double g_loss;
__device__ int    g_correct;
__device__ int    g_lab32;

// ---------------- smem layout (dynamic, bytes) ----------------
#define SM_CC    0          // 2048 floats = 8192
#define SM_LOGP  8192       // 128 floats
#define SM_CORR  8704       // 128 ints
#define SM_PD    9216       // 4 doubles
#define SM_PI    9248       // 4 ints
#define SM_Q     10240      // 128 rows x 1024B = 131072
#define SM_A     141312     // 64 rows x 1024B = 65536
#define SMEM_BYTES 206848

// ---------------- PTX helpers (portable: sm_80-level, OK for compute_103) ----
__device__ __forceinline__ uint32_t smem_u32(const void* p) {
    uint32_t a;
    asm("{ .reg .u64 t; cvta.to.shared.u64 t, %1; cvt.u32.u64 %0, t; }" : "=r"(a) : "l"(p));
    return a;
}
#define CP_ASYNC16(dst, src) \
    asm volatile("cp.async.cg.shared.global [%0], [%1], 16;" :: "r"(dst), "l"(src) : "memory")
#define CP_COMMIT() asm volatile("cp.async.commit_group;" ::: "memory")
#define CP_WAIT0()  asm volatile("cp.async.wait_group 0;" ::: "memory")

#define LDSM_X4(r0, r1, r2, r3, addr) \
    asm volatile("ldmatrix.sync.aligned.m8n8.x4.shared.b16 {%0,%1,%2,%3}, [%4];" \
        : "=r"(r0), "=r"(r1), "=r"(r2), "=r"(r3) : "r"(addr))

#define MMA16816(c, a0, a1, a2, a3, b0, b1) \
    asm volatile("mma.sync.aligned.m16n8k16.row.col.f32.f16.f16.f32 " \
        "{%0,%1,%2,%3}, {%4,%5,%6,%7}, {%8,%9}, {%0,%1,%2,%3};" \
        : "+f"((c)[0]), "+f"((c)[1]), "+f"((c)[2]), "+f"((c)[3]) \
        : "r"(a0), "r"(a1), "r"(a2), "r"(a3), "r"(b0), "r"(b1))

__device__ __forceinline__ float ex2f(float x) { float r; asm("ex2.approx.f32 %0, %1;" : "=f"(r) : "f"(x)); return r; }
__device__ __forceinline__ float lg2f(float x) { float r; asm("lg2.approx.f32 %0, %1;" : "=f"(r) : "f"(x)); return r; }

// ---------------- init: zero accumulators + label dtype sniff ----------------
__global__ void init_kernel(const unsigned long long* __restrict__ lab) {
    unsigned long long v = lab[threadIdx.x];
    unsigned b = __ballot_sync(0xFFFFFFFFu, (v >> 32) != 0ull);
    if (threadIdx.x == 0) { g_loss = 0.0; g_correct = 0; g_lab32 = (b != 0u) ? 1 : 0; }
}

// ---------------- prep: anchors -> fp16 hi/lo split + column constant -------
__global__ void prep_kernel(const float* __restrict__ x) {
    int i = blockIdx.x;
    int d = threadIdx.x;                       // 256 threads == D
    const float* xr = x + (size_t)i * SLOTS * D + d;
    float a = (xr[0] + xr[D] + xr[2 * D] + xr[3 * D] + xr[4 * D]) * 0.2f;

    __half hi = __float2half_rn(a);
    __half lo = __float2half_rn(a - __half2float(hi));
    g_aext[(size_t)i * KEXT + d]       = hi;
    g_aext[(size_t)i * KEXT + 256 + d] = lo;

    float sq = a * a, sm = a;
#pragma unroll
    for (int o = 16; o; o >>= 1) {
        sq += __shfl_xor_sync(0xFFFFFFFFu, sq, o);
        sm += __shfl_xor_sync(0xFFFFFFFFu, sm, o);
    }
    __shared__ float ssq[8], ssm[8];
    if ((threadIdx.x & 31) == 0) { ssq[threadIdx.x >> 5] = sq; ssm[threadIdx.x >> 5] = sm; }
    __syncthreads();
    if (threadIdx.x == 0) {
        float t1 = 0.f, t2 = 0.f;
#pragma unroll
        for (int k = 0; k < 8; k++) { t1 += ssq[k]; t2 += ssm[k]; }
        g_cc2[i] = (-t1 + 2.0f * EPS * t2) * LOG2E;
    }
}

// ---------------- fused HMMA GEMM + online softmax ---------------------------
extern __shared__ char dsm[];

__global__ void __launch_bounds__(128, 1) gemm_softmax_kernel(
    const float* __restrict__ x, const void* __restrict__ labraw) {
    const uint32_t sb = smem_u32(dsm);
    const int tid = threadIdx.x, wid = tid >> 5, lane = tid & 31;
    const int qid = lane & 3, g = lane >> 2;
    const int r0 = blockIdx.x * MT;

    // ---- stage column constants ----
#pragma unroll
    for (int i = tid; i < N_EP / 4; i += 128)
        ((float4*)(dsm + SM_CC))[i] = ((const float4*)g_cc2)[i];

    // ---- stage Q tile: fp32 -> fp16 hi/lo split, XOR-swizzled 1024B rows ----
#pragma unroll 2
    for (int i = 0; i < 64; i++) {
        int f = i * 128 + tid;            // 128 rows x 64 float4-segments
        int row = f >> 6, seg = f & 63;
        int r = r0 + row;
        const float4 v = *(const float4*)(x + ((size_t)(r >> 3) * SLOTS + NS + (r & 7)) * D + seg * 4);
        __half h0 = __float2half_rn(v.x), h1 = __float2half_rn(v.y);
        __half h2 = __float2half_rn(v.z), h3 = __float2half_rn(v.w);
        __half l0 = __float2half_rn(v.x - __half2float(h0));
        __half l1 = __float2half_rn(v.y - __half2float(h1));
        __half l2 = __float2half_rn(v.z - __half2float(h2));
        __half l3 = __float2half_rn(v.w - __half2float(h3));
        __half2 ph01 = __halves2half2(h0, h1), ph23 = __halves2half2(h2, h3);
        __half2 pl01 = __halves2half2(l0, l1), pl23 = __halves2half2(l2, l3);
        unsigned long long uh = ((unsigned long long)(*(uint32_t*)&ph23) << 32) | (*(uint32_t*)&ph01);
        unsigned long long ul = ((unsigned long long)(*(uint32_t*)&pl23) << 32) | (*(uint32_t*)&pl01);
        int rp = row & 7;
        int ch = seg >> 1;                 // hi chunk 0..31
        int sub = (seg & 1) * 8;
        *(unsigned long long*)(dsm + SM_Q + row * 1024 + ((ch ^ rp) << 4) + sub) = uh;
        int cl = 32 + ch;                  // lo chunk 32..63
        *(unsigned long long*)(dsm + SM_Q + row * 1024 + ((cl ^ rp) << 4) + sub) = ul;
    }

    // ---- labels for my 4 row-slices ----
    const int lab32 = g_lab32;
    int labs[4];
#pragma unroll
    for (int s = 0; s < 4; s++) {
        int row = wid * 32 + (s >> 1) * 16 + g + (s & 1) * 8;
        int ep = (r0 + row) >> 3;
        labs[s] = lab32 ? ((const int*)labraw)[ep] : (int)((const long long*)labraw)[ep];
    }

    // ---- ldmatrix address bases (fixed per thread) ----
    const int rowA = wid * 32 + (lane & 15);       // +16 for t=1 (low3 bits unchanged)
    const int cbA  = lane >> 4;                    // k-chunk select 0/1
    const uint32_t aBase0 = sb + SM_Q + rowA * 1024;
    const int rpA = rowA & 7;
    const int rowB = (lane >> 4) * 8 + (lane & 7); // n-row within 16-row pair
    const int ckB  = (lane >> 3) & 1;
    const uint32_t bBase = sb + SM_A + rowB * 1024;
    const int rpB = rowB & 7;

    // per-row-slice online softmax state
    float m2[4], s2[4], ll2[4], bv[4];
    int bi[4];
#pragma unroll
    for (int s = 0; s < 4; s++) { m2[s] = -1e30f; s2[s] = 0.f; ll2[s] = -1e30f; bv[s] = -1e30f; bi[s] = 0x7fffffff; }

    for (int nt = 0; nt < NTILES; nt++) {
        const int n0 = nt * NT;
        __syncthreads();   // all warps done reading previous A tile
        // ---- async-load anchor tile (64 x 1024B), swizzled ----
        {
            const char* asrc = (const char*)g_aext + (size_t)n0 * 1024;
#pragma unroll
            for (int i = 0; i < 32; i++) {
                int f = i * 128 + tid;
                int row = f >> 6, c = f & 63;
                uint32_t dst = sb + SM_A + row * 1024 + ((c ^ (row & 7)) << 4);
                CP_ASYNC16(dst, asrc + (size_t)row * 1024 + c * 16);
            }
            CP_COMMIT();
            CP_WAIT0();
        }
        __syncthreads();

        // ---- GEMM: 32 rows x 64 cols per warp over K=512 ----
        float c[2][8][4];
#pragma unroll
        for (int t = 0; t < 2; t++)
#pragma unroll
            for (int j = 0; j < 8; j++)
#pragma unroll
                for (int e = 0; e < 4; e++) c[t][j][e] = 0.f;

#pragma unroll 4
        for (int kc = 0; kc < NKC; kc++) {
            uint32_t a0[4], a1[4], b[4][4];
            int offA = (((2 * kc + cbA) ^ rpA) << 4);
            LDSM_X4(a0[0], a0[1], a0[2], a0[3], aBase0 + offA);
            LDSM_X4(a1[0], a1[1], a1[2], a1[3], aBase0 + 16 * 1024 + offA);
            int offB = (((2 * kc + ckB) ^ rpB) << 4);
#pragma unroll
            for (int p = 0; p < 4; p++)
                LDSM_X4(b[p][0], b[p][1], b[p][2], b[p][3], bBase + p * 16384 + offB);
#pragma unroll
            for (int j = 0; j < 8; j++) {
                uint32_t bb0 = b[j >> 1][(j & 1) * 2], bb1 = b[j >> 1][(j & 1) * 2 + 1];
                MMA16816(c[0][j], a0[0], a0[1], a0[2], a0[3], bb0, bb1);
                MMA16816(c[1][j], a1[0], a1[1], a1[2], a1[3], bb0, bb1);
            }
        }

        // ---- epilogue: per row-slice online softmax (quad = one row) ----
#pragma unroll
        for (int s = 0; s < 4; s++) {
            const int t = s >> 1, u = s & 1;
            float lg[8][2];
            float mx = -1e30f, bq = -1e30f, ll = -1e30f;
            int biq = 0x7fffffff;
#pragma unroll
            for (int j = 0; j < 8; j++) {
                float2 cv = *(const float2*)(dsm + SM_CC + (size_t)(n0 + j * 8 + qid * 2) * 4);
                float l0 = fmaf(c[t][j][u * 2 + 0], SC2, cv.x);
                float l1 = fmaf(c[t][j][u * 2 + 1], SC2, cv.y);
                lg[j][0] = l0; lg[j][1] = l1;
                mx = fmaxf(mx, fmaxf(l0, l1));
                int col0 = n0 + j * 8 + qid * 2;
                if (l0 > bq) { bq = l0; biq = col0; }
                if (l1 > bq) { bq = l1; biq = col0 + 1; }
                if (col0 == labs[s])     ll = l0;
                if (col0 + 1 == labs[s]) ll = l1;
            }
            // quad reductions (lanes qid 0..3 share the row)
#pragma unroll
            for (int o = 1; o <= 2; o <<= 1) {
                mx = fmaxf(mx, __shfl_xor_sync(0xFFFFFFFFu, mx, o));
                ll = fmaxf(ll, __shfl_xor_sync(0xFFFFFFFFu, ll, o));
                float ov = __shfl_xor_sync(0xFFFFFFFFu, bq, o);
                int   oi = __shfl_xor_sync(0xFFFFFFFFu, biq, o);
                if (ov > bq || (ov == bq && oi < biq)) { bq = ov; biq = oi; }
            }
            float newm = fmaxf(m2[s], mx);
            float p = 0.f;
#pragma unroll
            for (int j = 0; j < 8; j++) { p += ex2f(lg[j][0] - newm); p += ex2f(lg[j][1] - newm); }
#pragma unroll
            for (int o = 1; o <= 2; o <<= 1) p += __shfl_xor_sync(0xFFFFFFFFu, p, o);
            s2[s] = fmaf(s2[s], ex2f(m2[s] - newm), p);
            m2[s] = newm;
            ll2[s] = fmaxf(ll2[s], ll);
            if (bq > bv[s] || (bq == bv[s] && biq < bi[s])) { bv[s] = bq; bi[s] = biq; }
        }
    }

    // ---- finalize: canonical lane per quad writes per-row results ----
    if (qid == 0) {
#pragma unroll
        for (int s = 0; s < 4; s++) {
            int row = wid * 32 + (s >> 1) * 16 + g + (s & 1) * 8;
            ((float*)(dsm + SM_LOGP))[row] = ll2[s] - m2[s] - lg2f(s2[s]);
            ((int*)(dsm + SM_CORR))[row] = (bi[s] == labs[s]) ? 1 : 0;
        }
    }
    __syncthreads();
    {
        double ls = (double)((float*)(dsm + SM_LOGP))[tid] * LN2;
        int cs = ((int*)(dsm + SM_CORR))[tid];
#pragma unroll
        for (int o = 16; o; o >>= 1) {
            ls += __shfl_down_sync(0xFFFFFFFFu, ls, o);
            cs += __shfl_down_sync(0xFFFFFFFFu, cs, o);
        }
        if (lane == 0) { ((double*)(dsm + SM_PD))[wid] = ls; ((int*)(dsm + SM_PI))[wid] = cs; }
    }
    __syncthreads();
    if (tid == 0) {
        double ls = 0.0; int cs = 0;
#pragma unroll
        for (int w = 0; w < 4; w++) { ls += ((double*)(dsm + SM_PD))[w]; cs += ((int*)(dsm + SM_PI))[w]; }
        atomicAdd(&g_loss, ls);
        atomicAdd(&g_correct, cs);
    }
}

__global__ void final_kernel(float* out, int out_size) {
    if (out_size > 0) out[0] = (float)(-g_loss / (double)NROW);
    if (out_size > 1) out[1] = (float)g_correct * (100.0f / (float)NROW);
}

extern "C" void kernel_launch(void* const* d_in, const int* in_sizes, int n_in,
                              void* d_out, int out_size) {
    const float* x = (const float*)d_in[0];
    const unsigned long long* label = (const unsigned long long*)d_in[1];
    float* out = (float*)d_out;

    cudaFuncSetAttribute(gemm_softmax_kernel,
                         cudaFuncAttributeMaxDynamicSharedMemorySize, SMEM_BYTES);

    init_kernel<<<1, 32>>>(label);
    prep_kernel<<<N_EP, D>>>(x);
    gemm_softmax_kernel<<<NROW / MT, 128, SMEM_BYTES>>>(x, (const void*)label);
    final_kernel<<<1, 1>>>(out, out_size);
}

// round 6
// speedup vs baseline: 4.4839x; 1.2429x over previous
#include <cuda_runtime.h>
#include <cuda_fp16.h>
#include <math.h>
#include <stdint.h>

// ---------------- problem constants ----------------
#define EPS    1e-6f
#define N_EP   2048
#define NS     5
#define SLOTS  13
#define D      256
#define NROW   16384
#define KEXT   512              // [hi(256) | lo(256)] fp16 split
#define MT     128              // M rows per CTA
#define NT     64               // N cols per tile
#define NTILES (N_EP / NT)      // 32
#define NKC    (KEXT / 16)      // 32 k-steps
#define NTH    256
#define LOG2E  1.4426950408889634f
#define SC2    2.8853900817779268f   // 2*log2(e)
#define LN2    0.6931471805599453

// ---------------- device globals ----------------
__device__ __align__(256) __half g_aext[N_EP * KEXT];  // anchors split [n][512]
__device__ __align__(256) float  g_cc2[N_EP];          // (-a_sq + 2*eps*a_sum)*log2e
__device__ double g_loss;
__device__ int    g_correct;
__device__ int    g_lab32;

// ---------------- smem layout (dynamic, bytes) ----------------
#define SM_CC    0          // 2048 floats = 8192
#define SM_LOGP  8192       // 128 floats
#define SM_CORR  8704       // 128 ints
#define SM_PD    9216       // 4 doubles
#define SM_PI    9248       // 4 ints
#define SM_A0    10240      // 64 rows x 1024B = 65536
#define SM_Q     75776      // 128 rows x 1024B = 131072 (staging; freed after frag load)
#define SM_A1    75776      // aliases first 64KB of SM_Q
#define SMEM_BYTES 206848

// ---------------- PTX helpers (sm_80-level, portable to compute_103) --------
__device__ __forceinline__ uint32_t smem_u32(const void* p) {
    uint32_t a;
    asm("{ .reg .u64 t; cvta.to.shared.u64 t, %1; cvt.u32.u64 %0, t; }" : "=r"(a) : "l"(p));
    return a;
}
#define CP_ASYNC16(dst, src) \
    asm volatile("cp.async.cg.shared.global [%0], [%1], 16;" :: "r"(dst), "l"(src) : "memory")
#define CP_COMMIT() asm volatile("cp.async.commit_group;" ::: "memory")
#define CP_WAIT0()  asm volatile("cp.async.wait_group 0;" ::: "memory")
#define CP_WAIT1()  asm volatile("cp.async.wait_group 1;" ::: "memory")

#define LDSM_X4(r0, r1, r2, r3, addr) \
    asm volatile("ldmatrix.sync.aligned.m8n8.x4.shared.b16 {%0,%1,%2,%3}, [%4];" \
        : "=r"(r0), "=r"(r1), "=r"(r2), "=r"(r3) : "r"(addr))

#define MMA16816(c, a0, a1, a2, a3, b0, b1) \
    asm volatile("mma.sync.aligned.m16n8k16.row.col.f32.f16.f16.f32 " \
        "{%0,%1,%2,%3}, {%4,%5,%6,%7}, {%8,%9}, {%0,%1,%2,%3};" \
        : "+f"((c)[0]), "+f"((c)[1]), "+f"((c)[2]), "+f"((c)[3]) \
        : "r"(a0), "r"(a1), "r"(a2), "r"(a3), "r"(b0), "r"(b1))

__device__ __forceinline__ float ex2f(float x) { float r; asm("ex2.approx.f32 %0, %1;" : "=f"(r) : "f"(x)); return r; }
__device__ __forceinline__ float lg2f(float x) { float r; asm("lg2.approx.f32 %0, %1;" : "=f"(r) : "f"(x)); return r; }

// ---------------- init: zero accumulators + label dtype sniff ----------------
__global__ void init_kernel(const unsigned long long* __restrict__ lab) {
    unsigned long long v = lab[threadIdx.x];
    unsigned b = __ballot_sync(0xFFFFFFFFu, (v >> 32) != 0ull);
    if (threadIdx.x == 0) { g_loss = 0.0; g_correct = 0; g_lab32 = (b != 0u) ? 1 : 0; }
}

// ---------------- prep: anchors -> fp16 hi/lo split + column constant -------
__global__ void prep_kernel(const float* __restrict__ x) {
    int i = blockIdx.x;
    int d = threadIdx.x;                       // 256 threads == D
    const float* xr = x + (size_t)i * SLOTS * D + d;
    float a = (xr[0] + xr[D] + xr[2 * D] + xr[3 * D] + xr[4 * D]) * 0.2f;

    __half hi = __float2half_rn(a);
    __half lo = __float2half_rn(a - __half2float(hi));
    g_aext[(size_t)i * KEXT + d]       = hi;
    g_aext[(size_t)i * KEXT + 256 + d] = lo;

    float sq = a * a, sm = a;
#pragma unroll
    for (int o = 16; o; o >>= 1) {
        sq += __shfl_xor_sync(0xFFFFFFFFu, sq, o);
        sm += __shfl_xor_sync(0xFFFFFFFFu, sm, o);
    }
    __shared__ float ssq[8], ssm[8];
    if ((threadIdx.x & 31) == 0) { ssq[threadIdx.x >> 5] = sq; ssm[threadIdx.x >> 5] = sm; }
    __syncthreads();
    if (threadIdx.x == 0) {
        float t1 = 0.f, t2 = 0.f;
#pragma unroll
        for (int k = 0; k < 8; k++) { t1 += ssq[k]; t2 += ssm[k]; }
        g_cc2[i] = (-t1 + 2.0f * EPS * t2) * LOG2E;
    }
}

// ---------------- fused HMMA GEMM + online softmax ---------------------------
extern __shared__ char dsm[];

__global__ void __launch_bounds__(NTH, 1) gemm_softmax_kernel(
    const float* __restrict__ x, const void* __restrict__ labraw) {
    const uint32_t sb = smem_u32(dsm);
    const int tid = threadIdx.x, wid = tid >> 5, lane = tid & 31;
    const int qid = lane & 3, g = lane >> 2;
    const int r0 = blockIdx.x * MT;

    // ---- issue first A tile early (independent smem region) ----
    {
        const char* asrc = (const char*)g_aext;        // tile 0: anchors 0..63
#pragma unroll
        for (int i = 0; i < 16; i++) {
            int f = i * NTH + tid;                     // 64 rows x 64 16B-chunks
            int row = f >> 6, c = f & 63;
            uint32_t dst = sb + SM_A0 + row * 1024 + ((c ^ (row & 7)) << 4);
            CP_ASYNC16(dst, asrc + (size_t)row * 1024 + c * 16);
        }
        CP_COMMIT();
    }

    // ---- stage column constants ----
#pragma unroll
    for (int i = tid; i < N_EP / 4; i += NTH)
        ((float4*)(dsm + SM_CC))[i] = ((const float4*)g_cc2)[i];

    // ---- stage Q tile: fp32 -> fp16 hi/lo split, XOR-swizzled 1024B rows ----
#pragma unroll 2
    for (int i = 0; i < 32; i++) {
        int f = i * NTH + tid;            // 128 rows x 64 float4-segments
        int row = f >> 6, seg = f & 63;
        int r = r0 + row;
        const float4 v = *(const float4*)(x + ((size_t)(r >> 3) * SLOTS + NS + (r & 7)) * D + seg * 4);
        __half h0 = __float2half_rn(v.x), h1 = __float2half_rn(v.y);
        __half h2 = __float2half_rn(v.z), h3 = __float2half_rn(v.w);
        __half l0 = __float2half_rn(v.x - __half2float(h0));
        __half l1 = __float2half_rn(v.y - __half2float(h1));
        __half l2 = __float2half_rn(v.z - __half2float(h2));
        __half l3 = __float2half_rn(v.w - __half2float(h3));
        __half2 ph01 = __halves2half2(h0, h1), ph23 = __halves2half2(h2, h3);
        __half2 pl01 = __halves2half2(l0, l1), pl23 = __halves2half2(l2, l3);
        unsigned long long uh = ((unsigned long long)(*(uint32_t*)&ph23) << 32) | (*(uint32_t*)&ph01);
        unsigned long long ul = ((unsigned long long)(*(uint32_t*)&pl23) << 32) | (*(uint32_t*)&pl01);
        int rp = row & 7;
        int ch = seg >> 1;                 // hi chunk 0..31
        int sub = (seg & 1) * 8;
        *(unsigned long long*)(dsm + SM_Q + row * 1024 + ((ch ^ rp) << 4) + sub) = uh;
        int cl = 32 + ch;                  // lo chunk 32..63
        *(unsigned long long*)(dsm + SM_Q + row * 1024 + ((cl ^ rp) << 4) + sub) = ul;
    }
    __syncthreads();

    // ---- hoist Q fragments to registers (never re-read) ----
    const int rowA = wid * 16 + (lane & 15);
    const int cbA  = lane >> 4;
    const uint32_t aBase = sb + SM_Q + rowA * 1024;
    const int rpA = rowA & 7;
    uint32_t qf[NKC][4];
#pragma unroll
    for (int kc = 0; kc < NKC; kc++) {
        int offA = (((2 * kc + cbA) ^ rpA) << 4);
        LDSM_X4(qf[kc][0], qf[kc][1], qf[kc][2], qf[kc][3], aBase + offA);
    }
    __syncthreads();   // Q smem region now dead -> A1 may overwrite it

    // ---- issue A tile 1 into aliased buffer ----
    {
        const char* asrc = (const char*)g_aext + (size_t)NT * 1024;
#pragma unroll
        for (int i = 0; i < 16; i++) {
            int f = i * NTH + tid;
            int row = f >> 6, c = f & 63;
            uint32_t dst = sb + SM_A1 + row * 1024 + ((c ^ (row & 7)) << 4);
            CP_ASYNC16(dst, asrc + (size_t)row * 1024 + c * 16);
        }
        CP_COMMIT();
    }

    // ---- labels for my 2 row-slices ----
    const int lab32 = g_lab32;
    int labs[2];
#pragma unroll
    for (int s = 0; s < 2; s++) {
        int row = wid * 16 + g + s * 8;
        int ep = (r0 + row) >> 3;
        labs[s] = lab32 ? ((const int*)labraw)[ep] : (int)((const long long*)labraw)[ep];
    }

    // ---- B ldmatrix bases ----
    const int rowB = ((lane >> 4) * 8) + (lane & 7);
    const int ckB  = (lane >> 3) & 1;
    const int rpB  = rowB & 7;

    // per-(thread, row-slice) deferred online softmax state
    float m2[2], s2[2], ll2[2], bv[2];
    int bi[2];
#pragma unroll
    for (int s = 0; s < 2; s++) { m2[s] = -1e30f; s2[s] = 0.f; ll2[s] = -1e30f; bv[s] = -1e30f; bi[s] = 0x7fffffff; }

#pragma unroll 1
    for (int nt = 0; nt < NTILES; nt++) {
        const int n0 = nt * NT;
        if (nt < NTILES - 1) { CP_WAIT1(); } else { CP_WAIT0(); }
        __syncthreads();
        const uint32_t bufB = ((nt & 1) ? (sb + SM_A1) : (sb + SM_A0)) + rowB * 1024;

        // ---- GEMM: 16 rows x 64 cols per warp over K=512 ----
        float c[8][4];
#pragma unroll
        for (int j = 0; j < 8; j++)
#pragma unroll
            for (int e = 0; e < 4; e++) c[j][e] = 0.f;

#pragma unroll
        for (int kc = 0; kc < NKC; kc++) {
            uint32_t b[4][4];
            int offB = (((2 * kc + ckB) ^ rpB) << 4);
#pragma unroll
            for (int p = 0; p < 4; p++)
                LDSM_X4(b[p][0], b[p][1], b[p][2], b[p][3], bufB + p * 16384 + offB);
#pragma unroll
            for (int j = 0; j < 8; j++)
                MMA16816(c[j], qf[kc][0], qf[kc][1], qf[kc][2], qf[kc][3],
                         b[j >> 1][(j & 1) * 2], b[j >> 1][(j & 1) * 2 + 1]);
        }
        __syncthreads();   // all warps done reading buf (nt&1) before refill
        if (nt + 2 < NTILES) {
            const char* asrc = (const char*)g_aext + (size_t)(n0 + 2 * NT) * 1024;
            const uint32_t dbuf = (nt & 1) ? (sb + SM_A1) : (sb + SM_A0);
#pragma unroll
            for (int i = 0; i < 16; i++) {
                int f = i * NTH + tid;
                int row = f >> 6, cc = f & 63;
                CP_ASYNC16(dbuf + row * 1024 + ((cc ^ (row & 7)) << 4),
                           asrc + (size_t)row * 1024 + cc * 16);
            }
            CP_COMMIT();
        }

        // ---- epilogue: per-thread online softmax over own 16 cols/slice ----
#pragma unroll
        for (int s = 0; s < 2; s++) {
            float lg[8][2];
            float mx = -1e30f;
#pragma unroll
            for (int j = 0; j < 8; j++) {
                float2 cv = *(const float2*)(dsm + SM_CC + (size_t)(n0 + j * 8 + qid * 2) * 4);
                float l0 = fmaf(c[j][s * 2 + 0], SC2, cv.x);
                float l1 = fmaf(c[j][s * 2 + 1], SC2, cv.y);
                lg[j][0] = l0; lg[j][1] = l1;
                mx = fmaxf(mx, fmaxf(l0, l1));
                int col0 = n0 + j * 8 + qid * 2;
                if (l0 > bv[s]) { bv[s] = l0; bi[s] = col0; }
                if (l1 > bv[s]) { bv[s] = l1; bi[s] = col0 + 1; }
                if (col0 == labs[s])     ll2[s] = l0;
                if (col0 + 1 == labs[s]) ll2[s] = l1;
            }
            float newm = fmaxf(m2[s], mx);
            float p = 0.f;
#pragma unroll
            for (int j = 0; j < 8; j++) { p += ex2f(lg[j][0] - newm); p += ex2f(lg[j][1] - newm); }
            s2[s] = fmaf(s2[s], ex2f(m2[s] - newm), p);
            m2[s] = newm;
        }
    }

    // ---- final cross-quad merge (once) ----
#pragma unroll
    for (int s = 0; s < 2; s++) {
#pragma unroll
        for (int o = 1; o <= 2; o <<= 1) {
            float om = __shfl_xor_sync(0xFFFFFFFFu, m2[s], o);
            float os = __shfl_xor_sync(0xFFFFFFFFu, s2[s], o);
            float nm = fmaxf(m2[s], om);
            s2[s] = s2[s] * ex2f(m2[s] - nm) + os * ex2f(om - nm);
            m2[s] = nm;
            ll2[s] = fmaxf(ll2[s], __shfl_xor_sync(0xFFFFFFFFu, ll2[s], o));
            float ov = __shfl_xor_sync(0xFFFFFFFFu, bv[s], o);
            int   oi = __shfl_xor_sync(0xFFFFFFFFu, bi[s], o);
            if (ov > bv[s] || (ov == bv[s] && oi < bi[s])) { bv[s] = ov; bi[s] = oi; }
        }
        if (qid == 0) {
            int row = wid * 16 + g + s * 8;
            ((float*)(dsm + SM_LOGP))[row] = ll2[s] - m2[s] - lg2f(s2[s]);
            ((int*)(dsm + SM_CORR))[row] = (bi[s] == labs[s]) ? 1 : 0;
        }
    }
    __syncthreads();

    if (tid < 128) {
        double ls = (double)((float*)(dsm + SM_LOGP))[tid] * LN2;
        int cs = ((int*)(dsm + SM_CORR))[tid];
#pragma unroll
        for (int o = 16; o; o >>= 1) {
            ls += __shfl_down_sync(0xFFFFFFFFu, ls, o);
            cs += __shfl_down_sync(0xFFFFFFFFu, cs, o);
        }
        if (lane == 0) { ((double*)(dsm + SM_PD))[wid] = ls; ((int*)(dsm + SM_PI))[wid] = cs; }
    }
    __syncthreads();
    if (tid == 0) {
        double ls = 0.0; int cs = 0;
#pragma unroll
        for (int w = 0; w < 4; w++) { ls += ((double*)(dsm + SM_PD))[w]; cs += ((int*)(dsm + SM_PI))[w]; }
        atomicAdd(&g_loss, ls);
        atomicAdd(&g_correct, cs);
    }
}

__global__ void final_kernel(float* out, int out_size) {
    if (out_size > 0) out[0] = (float)(-g_loss / (double)NROW);
    if (out_size > 1) out[1] = (float)g_correct * (100.0f / (float)NROW);
}

extern "C" void kernel_launch(void* const* d_in, const int* in_sizes, int n_in,
                              void* d_out, int out_size) {
    const float* x = (const float*)d_in[0];
    const unsigned long long* label = (const unsigned long long*)d_in[1];
    float* out = (float*)d_out;

    cudaFuncSetAttribute(gemm_softmax_kernel,
                         cudaFuncAttributeMaxDynamicSharedMemorySize, SMEM_BYTES);

    init_kernel<<<1, 32>>>(label);
    prep_kernel<<<N_EP, D>>>(x);
    gemm_softmax_kernel<<<NROW / MT, NTH, SMEM_BYTES>>>(x, (const void*)label);
    final_kernel<<<1, 1>>>(out, out_size);
}